// round 3
// baseline (speedup 1.0000x reference)
#include <cuda_runtime.h>
#include <math.h>

#define L_SEQ  2048
#define BATCH  2
#define DMODEL 1024
#define NHEAD  16
#define HDIM   64

// Scratch (allocation-free rule: __device__ globals)
__device__ float g_qkv[BATCH * L_SEQ * 3 * DMODEL];   // [B,L,3D]
__device__ float g_y[BATCH * L_SEQ * DMODEL];         // [B,L,D]

// ---------------------------------------------------------------------------
// Classic 128x128x8 SGEMM, 256 threads, 8x8 per-thread tile, fp32.
// C[M,N] = A[M,K] @ B[K,N], all row-major, dims divisible by tiles.
// ---------------------------------------------------------------------------
__global__ __launch_bounds__(256) void sgemm_kernel(
    int M, int N, int K,
    const float* __restrict__ A, const float* __restrict__ B,
    float* __restrict__ C)
{
    constexpr int BM = 128, BN = 128, BK = 8, TM = 8, TN = 8;
    __shared__ float As[BK][BM];
    __shared__ float Bs[BK][BN];

    const int tid = threadIdx.x;
    const int tr = tid / 16;          // 0..15 : row tile
    const int tc = tid % 16;          // 0..15 : col tile
    const int rowA = tid / 2;         // 0..127
    const int colA = (tid % 2) * 4;   // 0 or 4
    const int rowB = tid / 32;        // 0..7
    const int colB = (tid % 32) * 4;  // 0..124

    const float* Ab = A + (size_t)blockIdx.y * BM * K;
    const float* Bb = B + (size_t)blockIdx.x * BN;
    float* Cb = C + (size_t)blockIdx.y * BM * N + (size_t)blockIdx.x * BN;

    float acc[TM][TN] = {};
    float regM[TM], regN[TN];

    for (int k0 = 0; k0 < K; k0 += BK) {
        float4 a4 = *(const float4*)(Ab + (size_t)rowA * K + k0 + colA);
        As[colA + 0][rowA] = a4.x;
        As[colA + 1][rowA] = a4.y;
        As[colA + 2][rowA] = a4.z;
        As[colA + 3][rowA] = a4.w;
        *(float4*)(&Bs[rowB][colB]) =
            *(const float4*)(Bb + (size_t)(k0 + rowB) * N + colB);
        __syncthreads();

#pragma unroll
        for (int k = 0; k < BK; k++) {
            *(float4*)&regM[0] = *(float4*)&As[k][tr * TM];
            *(float4*)&regM[4] = *(float4*)&As[k][tr * TM + 4];
            *(float4*)&regN[0] = *(float4*)&Bs[k][tc * TN];
            *(float4*)&regN[4] = *(float4*)&Bs[k][tc * TN + 4];
#pragma unroll
            for (int i = 0; i < TM; i++)
#pragma unroll
                for (int j = 0; j < TN; j++)
                    acc[i][j] = fmaf(regM[i], regN[j], acc[i][j]);
        }
        __syncthreads();
    }

#pragma unroll
    for (int i = 0; i < TM; i++) {
        float* cr = Cb + (size_t)(tr * TM + i) * N + tc * TN;
        *(float4*)(cr + 0) = make_float4(acc[i][0], acc[i][1], acc[i][2], acc[i][3]);
        *(float4*)(cr + 4) = make_float4(acc[i][4], acc[i][5], acc[i][6], acc[i][7]);
    }
}

// ---------------------------------------------------------------------------
// Flash-attention with dual scores. One CTA = (b, h, 64-query block).
// Q/Qg and K/Kg are concatenated along d (effective hd = 128) so
// S = Q·K^T + Qg·Kg^T is a single accumulation.
// 256 threads as (ty,tx) = (tid/16, tid%16); thread owns rows {ty+16i},
// cols {tx+16j} (strided 4x4 -> conflict-free smem b-loads, shuffle-only
// row reductions within 16-lane groups).
// ---------------------------------------------------------------------------
#define QKS 129   // row stride for 128-wide Q/K tiles (odd -> conflict-free)
#define VS  65    // row stride for 64-wide V/P tiles

__global__ __launch_bounds__(256, 2) void attn_kernel(
    const float* __restrict__ qg_in, const float* __restrict__ kg_in)
{
    extern __shared__ float sm[];
    float* Qs = sm;                    // [64][QKS]
    float* Ks = sm + 64 * QKS;         // [64][QKS]
    float* Vs = sm + 2 * 64 * QKS;     // [64][VS]
    float* Ps = Vs + 64 * VS;          // [64][VS]

    const int qb = blockIdx.x;   // query block 0..31
    const int h  = blockIdx.y;
    const int b  = blockIdx.z;
    const int tid = threadIdx.x;
    const int ty = tid >> 4;     // 0..15
    const int tx = tid & 15;     // 0..15
    const int q0 = qb * 64;

    // combined multiplier: (1/sqrt(hd)) / (log(L) * TEMPERATURE)
    const float Cmul = 0.125f / logf((float)L_SEQ);

    // ---- load Q tile (q cols 0..63, qg cols 64..127) ----
    for (int t = tid; t < 64 * 16; t += 256) {
        const int r  = t >> 4;
        const int c4 = (t & 15) << 2;
        const int row = b * L_SEQ + q0 + r;
        float4 q4 = *(const float4*)(g_qkv + (size_t)row * (3 * DMODEL) + h * HDIM + c4);
        float4 g4 = *(const float4*)(qg_in + (size_t)row * DMODEL + h * HDIM + c4);
        Qs[r * QKS + c4 + 0] = q4.x;
        Qs[r * QKS + c4 + 1] = q4.y;
        Qs[r * QKS + c4 + 2] = q4.z;
        Qs[r * QKS + c4 + 3] = q4.w;
        Qs[r * QKS + 64 + c4 + 0] = g4.x;
        Qs[r * QKS + 64 + c4 + 1] = g4.y;
        Qs[r * QKS + 64 + c4 + 2] = g4.z;
        Qs[r * QKS + 64 + c4 + 3] = g4.w;
    }

    float O[4][4] = {};
    float m[4], l[4];
#pragma unroll
    for (int i = 0; i < 4; i++) { m[i] = -INFINITY; l[i] = 0.0f; }

    for (int jb = 0; jb <= qb; jb++) {
        const int k0 = jb * 64;
        __syncthreads();  // prev PV done reading Vs/Ps; (iter 0: before K load)

        // ---- load K/Kg tile + V tile ----
        for (int t = tid; t < 64 * 16; t += 256) {
            const int r  = t >> 4;
            const int c4 = (t & 15) << 2;
            const int row = b * L_SEQ + k0 + r;
            const size_t base = (size_t)row * (3 * DMODEL) + h * HDIM + c4;
            float4 k4 = *(const float4*)(g_qkv + base + DMODEL);
            float4 v4 = *(const float4*)(g_qkv + base + 2 * DMODEL);
            float4 g4 = *(const float4*)(kg_in + (size_t)row * DMODEL + h * HDIM + c4);
            Ks[r * QKS + c4 + 0] = k4.x;
            Ks[r * QKS + c4 + 1] = k4.y;
            Ks[r * QKS + c4 + 2] = k4.z;
            Ks[r * QKS + c4 + 3] = k4.w;
            Ks[r * QKS + 64 + c4 + 0] = g4.x;
            Ks[r * QKS + 64 + c4 + 1] = g4.y;
            Ks[r * QKS + 64 + c4 + 2] = g4.z;
            Ks[r * QKS + 64 + c4 + 3] = g4.w;
            Vs[r * VS + c4 + 0] = v4.x;
            Vs[r * VS + c4 + 1] = v4.y;
            Vs[r * VS + c4 + 2] = v4.z;
            Vs[r * VS + c4 + 3] = v4.w;
        }
        __syncthreads();

        // ---- S = (Q|Qg) · (K|Kg)^T over d=0..127 ----
        float s[4][4] = {};
#pragma unroll 8
        for (int d = 0; d < 128; d++) {
            float a0 = Qs[(ty     ) * QKS + d];
            float a1 = Qs[(ty + 16) * QKS + d];
            float a2 = Qs[(ty + 32) * QKS + d];
            float a3 = Qs[(ty + 48) * QKS + d];
            float b0 = Ks[(tx     ) * QKS + d];
            float b1 = Ks[(tx + 16) * QKS + d];
            float b2 = Ks[(tx + 32) * QKS + d];
            float b3 = Ks[(tx + 48) * QKS + d];
            s[0][0] = fmaf(a0, b0, s[0][0]); s[0][1] = fmaf(a0, b1, s[0][1]);
            s[0][2] = fmaf(a0, b2, s[0][2]); s[0][3] = fmaf(a0, b3, s[0][3]);
            s[1][0] = fmaf(a1, b0, s[1][0]); s[1][1] = fmaf(a1, b1, s[1][1]);
            s[1][2] = fmaf(a1, b2, s[1][2]); s[1][3] = fmaf(a1, b3, s[1][3]);
            s[2][0] = fmaf(a2, b0, s[2][0]); s[2][1] = fmaf(a2, b1, s[2][1]);
            s[2][2] = fmaf(a2, b2, s[2][2]); s[2][3] = fmaf(a2, b3, s[2][3]);
            s[3][0] = fmaf(a3, b0, s[3][0]); s[3][1] = fmaf(a3, b1, s[3][1]);
            s[3][2] = fmaf(a3, b2, s[3][2]); s[3][3] = fmaf(a3, b3, s[3][3]);
        }

        // ---- scale + causal mask (diagonal block only) ----
        const bool diag = (jb == qb);
#pragma unroll
        for (int i = 0; i < 4; i++)
#pragma unroll
            for (int j = 0; j < 4; j++) {
                float v = s[i][j] * Cmul;
                if (diag && (tx + 16 * j) > (ty + 16 * i)) v = -INFINITY;
                s[i][j] = v;
            }

        // ---- online softmax (row reductions across tx: 16-lane butterflies) ----
#pragma unroll
        for (int i = 0; i < 4; i++) {
            float tm = fmaxf(fmaxf(s[i][0], s[i][1]), fmaxf(s[i][2], s[i][3]));
#pragma unroll
            for (int o = 8; o >= 1; o >>= 1)
                tm = fmaxf(tm, __shfl_xor_sync(0xffffffffu, tm, o));
            const float mn = fmaxf(m[i], tm);
            const float alpha = __expf(m[i] - mn);
            m[i] = mn;
            float rs = 0.0f;
#pragma unroll
            for (int j = 0; j < 4; j++) {
                float p = __expf(s[i][j] - mn);
                s[i][j] = p;
                rs += p;
            }
#pragma unroll
            for (int o = 8; o >= 1; o >>= 1)
                rs += __shfl_xor_sync(0xffffffffu, rs, o);
            l[i] = l[i] * alpha + rs;
#pragma unroll
            for (int j = 0; j < 4; j++) O[i][j] *= alpha;
#pragma unroll
            for (int j = 0; j < 4; j++)
                Ps[(ty + 16 * i) * VS + tx + 16 * j] = s[i][j];
        }
        __syncthreads();

        // ---- O += P @ V ----
#pragma unroll 4
        for (int k = 0; k < 64; k++) {
            float p0 = Ps[(ty     ) * VS + k];
            float p1 = Ps[(ty + 16) * VS + k];
            float p2 = Ps[(ty + 32) * VS + k];
            float p3 = Ps[(ty + 48) * VS + k];
            float v0 = Vs[k * VS + tx     ];
            float v1 = Vs[k * VS + tx + 16];
            float v2 = Vs[k * VS + tx + 32];
            float v3 = Vs[k * VS + tx + 48];
            O[0][0] = fmaf(p0, v0, O[0][0]); O[0][1] = fmaf(p0, v1, O[0][1]);
            O[0][2] = fmaf(p0, v2, O[0][2]); O[0][3] = fmaf(p0, v3, O[0][3]);
            O[1][0] = fmaf(p1, v0, O[1][0]); O[1][1] = fmaf(p1, v1, O[1][1]);
            O[1][2] = fmaf(p1, v2, O[1][2]); O[1][3] = fmaf(p1, v3, O[1][3]);
            O[2][0] = fmaf(p2, v0, O[2][0]); O[2][1] = fmaf(p2, v1, O[2][1]);
            O[2][2] = fmaf(p2, v2, O[2][2]); O[2][3] = fmaf(p2, v3, O[2][3]);
            O[3][0] = fmaf(p3, v0, O[3][0]); O[3][1] = fmaf(p3, v1, O[3][1]);
            O[3][2] = fmaf(p3, v2, O[3][2]); O[3][3] = fmaf(p3, v3, O[3][3]);
        }
    }

    // ---- epilogue: y[b, q, h*hd + d] = O / l ----
#pragma unroll
    for (int i = 0; i < 4; i++) {
        const float inv = 1.0f / l[i];
        const int row = b * L_SEQ + q0 + ty + 16 * i;
#pragma unroll
        for (int j = 0; j < 4; j++)
            g_y[(size_t)row * DMODEL + h * HDIM + tx + 16 * j] = O[i][j] * inv;
    }
}

// ---------------------------------------------------------------------------
extern "C" void kernel_launch(void* const* d_in, const int* in_sizes, int n_in,
                              void* d_out, int out_size)
{
    const float* x     = (const float*)d_in[0];
    const float* q_g   = (const float*)d_in[1];
    const float* k_g   = (const float*)d_in[2];
    const float* W_qkv = (const float*)d_in[3];
    const float* W_out = (const float*)d_in[4];
    float* out = (float*)d_out;

    float *qkv_ptr, *y_ptr;
    cudaGetSymbolAddress((void**)&qkv_ptr, g_qkv);
    cudaGetSymbolAddress((void**)&y_ptr, g_y);

    const int M = BATCH * L_SEQ;          // 4096

    // 1) qkv = x @ W_qkv   [4096,1024] x [1024,3072]
    {
        dim3 grid(3 * DMODEL / 128, M / 128);
        sgemm_kernel<<<grid, 256>>>(M, 3 * DMODEL, DMODEL, x, W_qkv, qkv_ptr);
    }

    // 2) attention
    {
        const int smem = (2 * 64 * QKS + 2 * 64 * VS) * (int)sizeof(float); // ~97KB
        cudaFuncSetAttribute(attn_kernel,
                             cudaFuncAttributeMaxDynamicSharedMemorySize, smem);
        dim3 grid(L_SEQ / 64, NHEAD, BATCH);
        attn_kernel<<<grid, 256, smem>>>(q_g, k_g);
    }

    // 3) out = y @ W_out   [4096,1024] x [1024,1024]
    {
        dim3 grid(DMODEL / 128, M / 128);
        sgemm_kernel<<<grid, 256>>>(M, DMODEL, DMODEL, y_ptr, W_out, out);
    }
}

// round 10
// speedup vs baseline: 2.3676x; 2.3676x over previous
#include <cuda_runtime.h>
#include <cuda_bf16.h>
#include <stdint.h>
#include <math.h>

#define L_SEQ  2048
#define BATCH  2
#define DMODEL 1024
#define NHEAD  16
#define HDIM   64

#define MROWS (BATCH * L_SEQ)         /* 4096 */

// ---------------- scratch (allocation-free rule: __device__ globals) -------
__device__ float        g_qkv[MROWS * 3 * DMODEL];            // fp32 [4096,3072]
__device__ __nv_bfloat16 g_xhi[MROWS * DMODEL];
__device__ __nv_bfloat16 g_xlo[MROWS * DMODEL];
__device__ __nv_bfloat16 g_yhi[MROWS * DMODEL];
__device__ __nv_bfloat16 g_ylo[MROWS * DMODEL];
__device__ __nv_bfloat16 g_wqT_hi[3 * DMODEL * DMODEL];       // W_qkv^T [3072,1024]
__device__ __nv_bfloat16 g_wqT_lo[3 * DMODEL * DMODEL];
__device__ __nv_bfloat16 g_woT_hi[DMODEL * DMODEL];           // W_out^T [1024,1024]
__device__ __nv_bfloat16 g_woT_lo[DMODEL * DMODEL];

// ---------------- helpers ---------------------------------------------------
__device__ __forceinline__ uint32_t smem_u32(const void* p) {
    uint32_t a;
    asm("{ .reg .u64 t; cvta.to.shared.u64 t, %1; cvt.u32.u64 %0, t; }"
        : "=r"(a) : "l"(p));
    return a;
}
__device__ __forceinline__ void cp16(uint32_t dst, const void* src) {
    asm volatile("cp.async.cg.shared.global [%0], [%1], 16;"
                 :: "r"(dst), "l"(src) : "memory");
}
__device__ __forceinline__ void ldsm_x4(uint32_t* r, uint32_t addr) {
    asm volatile("ldmatrix.sync.aligned.m8n8.x4.shared.b16 {%0,%1,%2,%3}, [%4];"
                 : "=r"(r[0]), "=r"(r[1]), "=r"(r[2]), "=r"(r[3]) : "r"(addr));
}
__device__ __forceinline__ void ldsm_x2(uint32_t* r, uint32_t addr) {
    asm volatile("ldmatrix.sync.aligned.m8n8.x2.shared.b16 {%0,%1}, [%2];"
                 : "=r"(r[0]), "=r"(r[1]) : "r"(addr));
}
__device__ __forceinline__ void mma_16816(float* d, const uint32_t* a, const uint32_t* b) {
    asm volatile(
        "mma.sync.aligned.m16n8k16.row.col.f32.bf16.bf16.f32 "
        "{%0,%1,%2,%3}, {%4,%5,%6,%7}, {%8,%9}, {%0,%1,%2,%3};"
        : "+f"(d[0]), "+f"(d[1]), "+f"(d[2]), "+f"(d[3])
        : "r"(a[0]), "r"(a[1]), "r"(a[2]), "r"(a[3]), "r"(b[0]), "r"(b[1]));
}

// ---------------------------------------------------------------------------
// Split-fp32 conversion passes (memory bound).
// ---------------------------------------------------------------------------
__global__ void cvt_split_kernel(const float* __restrict__ in,
                                 __nv_bfloat16* __restrict__ hi,
                                 __nv_bfloat16* __restrict__ lo, int n4)
{
    int i = blockIdx.x * blockDim.x + threadIdx.x;
    if (i >= n4) return;
    float4 v = ((const float4*)in)[i];
    __nv_bfloat162 h01, h23, l01, l23;
    h01.x = __float2bfloat16_rn(v.x); h01.y = __float2bfloat16_rn(v.y);
    h23.x = __float2bfloat16_rn(v.z); h23.y = __float2bfloat16_rn(v.w);
    l01.x = __float2bfloat16_rn(v.x - __bfloat162float(h01.x));
    l01.y = __float2bfloat16_rn(v.y - __bfloat162float(h01.y));
    l23.x = __float2bfloat16_rn(v.z - __bfloat162float(h23.x));
    l23.y = __float2bfloat16_rn(v.w - __bfloat162float(h23.y));
    ((__nv_bfloat162*)hi)[2 * i]     = h01;
    ((__nv_bfloat162*)hi)[2 * i + 1] = h23;
    ((__nv_bfloat162*)lo)[2 * i]     = l01;
    ((__nv_bfloat162*)lo)[2 * i + 1] = l23;
}

// W [K,N] fp32 -> Wt_hi/lo [N,K] bf16 (transpose + split)
__global__ void cvt_transpose_kernel(const float* __restrict__ W,
                                     __nv_bfloat16* __restrict__ Thi,
                                     __nv_bfloat16* __restrict__ Tlo,
                                     int K, int N)
{
    __shared__ float t[32][33];
    const int n0 = blockIdx.x * 32, k0 = blockIdx.y * 32;
    const int tx = threadIdx.x, ty = threadIdx.y;
#pragma unroll
    for (int j = 0; j < 32; j += 8)
        t[ty + j][tx] = W[(size_t)(k0 + ty + j) * N + n0 + tx];
    __syncthreads();
#pragma unroll
    for (int j = 0; j < 32; j += 8) {
        float v = t[tx][ty + j];
        size_t o = (size_t)(n0 + ty + j) * K + k0 + tx;
        __nv_bfloat16 h = __float2bfloat16_rn(v);
        Thi[o] = h;
        Tlo[o] = __float2bfloat16_rn(v - __bfloat162float(h));
    }
}

// ---------------------------------------------------------------------------
// HMMA split-bf16 GEMM: C[M,N] fp32 = A[M,K] x Bt[N,K]^T, 3-term hi/lo.
// 128x128 CTA tile, 8 warps (64x32 each), K-chunk 64, cp.async double buffer.
// smem per stage: Ahi|Alo|Bhi|Blo, each 128x64 bf16 (16KB) with XOR swizzle.
// ---------------------------------------------------------------------------
#define GSTAGE   65536                 /* 4 * 16KB */
#define GEMM_SMEM (2 * GSTAGE)         /* 128KB */

__device__ __forceinline__ uint32_t swz(int r, int cu) {
    return (uint32_t)(r * 128 + ((cu ^ (r & 7)) << 4));
}

__global__ __launch_bounds__(256, 1) void hmma_gemm_kernel(
    int M, int N, int K,
    const __nv_bfloat16* __restrict__ Ahi, const __nv_bfloat16* __restrict__ Alo,
    const __nv_bfloat16* __restrict__ Bhi, const __nv_bfloat16* __restrict__ Blo,
    float* __restrict__ C)
{
    extern __shared__ char smem[];
    const uint32_t sbase = smem_u32(smem);
    const int tid = threadIdx.x;
    const int wid = tid >> 5;
    const int lane = tid & 31;
    const int m0 = blockIdx.y * 128;
    const int n0 = blockIdx.x * 128;
    const int wm = wid & 1;            // 2 m-tiles of 64
    const int wn = wid >> 1;           // 4 n-tiles of 32

    const __nv_bfloat16* srcs[4] = {
        Ahi + (size_t)m0 * K, Alo + (size_t)m0 * K,
        Bhi + (size_t)n0 * K, Blo + (size_t)n0 * K };

    float acc[4][4][4] = {};

    const int nch = K >> 6;

    // stage chunk c into buffer c&1
    auto stage = [&](int c) {
        const int k0 = c << 6;
        const uint32_t sb = sbase + (uint32_t)(c & 1) * GSTAGE;
#pragma unroll
        for (int t = 0; t < 4; t++) {
            const __nv_bfloat16* src = srcs[t] + k0;
#pragma unroll
            for (int i = 0; i < 4; i++) {
                int u = tid + i * 256;         // 0..1023
                int r = u >> 3, cu = u & 7;
                cp16(sb + t * 16384 + swz(r, cu), src + (size_t)r * K + cu * 8);
            }
        }
    };

    stage(0);
    asm volatile("cp.async.commit_group;" ::: "memory");

    for (int c = 0; c < nch; c++) {
        if (c + 1 < nch) {
            stage(c + 1);
            asm volatile("cp.async.commit_group;" ::: "memory");
            asm volatile("cp.async.wait_group 1;" ::: "memory");
        } else {
            asm volatile("cp.async.wait_group 0;" ::: "memory");
        }
        __syncthreads();

        const uint32_t sb = sbase + (uint32_t)(c & 1) * GSTAGE;
        const int am = wm * 64, bn = wn * 32;
#pragma unroll
        for (int ks = 0; ks < 4; ks++) {
            uint32_t aH[4][4], aL[4][4], bH[4][2], bL[4][2];
            const int acu = ks * 2 + (lane >> 4);
            const int arow = lane & 15;
#pragma unroll
            for (int mi = 0; mi < 4; mi++) {
                int r = am + mi * 16 + arow;
                uint32_t ad = sb + swz(r, acu);
                ldsm_x4(aH[mi], ad);
                ldsm_x4(aL[mi], ad + 16384);
            }
            const int bcu = ks * 2 + ((lane >> 3) & 1);
            const int brow = lane & 7;
#pragma unroll
            for (int ni = 0; ni < 4; ni++) {
                int r = bn + ni * 8 + brow;
                uint32_t bd = sb + 32768 + swz(r, bcu);
                ldsm_x2(bH[ni], bd);
                ldsm_x2(bL[ni], bd + 16384);
            }
#pragma unroll
            for (int mi = 0; mi < 4; mi++)
#pragma unroll
                for (int ni = 0; ni < 4; ni++) {
                    mma_16816(acc[mi][ni], aH[mi], bH[ni]);
                    mma_16816(acc[mi][ni], aH[mi], bL[ni]);
                    mma_16816(acc[mi][ni], aL[mi], bH[ni]);
                }
        }
        __syncthreads();
    }

    // epilogue
#pragma unroll
    for (int mi = 0; mi < 4; mi++) {
        const int row = m0 + wm * 64 + mi * 16 + (lane >> 2);
#pragma unroll
        for (int ni = 0; ni < 4; ni++) {
            const int col = n0 + wn * 32 + ni * 8 + (lane & 3) * 2;
            float2 v01 = make_float2(acc[mi][ni][0], acc[mi][ni][1]);
            float2 v23 = make_float2(acc[mi][ni][2], acc[mi][ni][3]);
            *(float2*)(C + (size_t)row * N + col) = v01;
            *(float2*)(C + (size_t)(row + 8) * N + col) = v23;
        }
    }
}

// ---------------------------------------------------------------------------
// Flash-attention with dual scores (fp32 SIMT, proven R3 version).
// Epilogue writes y as split hi/lo bf16 for the out-projection GEMM.
// ---------------------------------------------------------------------------
#define QKS 129
#define VS  65

__global__ __launch_bounds__(256, 2) void attn_kernel(
    const float* __restrict__ qg_in, const float* __restrict__ kg_in)
{
    extern __shared__ float sm[];
    float* Qs = sm;
    float* Ks = sm + 64 * QKS;
    float* Vs = sm + 2 * 64 * QKS;
    float* Ps = Vs + 64 * VS;

    const int qb = blockIdx.x;
    const int h  = blockIdx.y;
    const int b  = blockIdx.z;
    const int tid = threadIdx.x;
    const int ty = tid >> 4;
    const int tx = tid & 15;
    const int q0 = qb * 64;

    const float Cmul = 0.125f / logf((float)L_SEQ);

    for (int t = tid; t < 64 * 16; t += 256) {
        const int r  = t >> 4;
        const int c4 = (t & 15) << 2;
        const int row = b * L_SEQ + q0 + r;
        float4 q4 = *(const float4*)(g_qkv + (size_t)row * (3 * DMODEL) + h * HDIM + c4);
        float4 g4 = *(const float4*)(qg_in + (size_t)row * DMODEL + h * HDIM + c4);
        Qs[r * QKS + c4 + 0] = q4.x; Qs[r * QKS + c4 + 1] = q4.y;
        Qs[r * QKS + c4 + 2] = q4.z; Qs[r * QKS + c4 + 3] = q4.w;
        Qs[r * QKS + 64 + c4 + 0] = g4.x; Qs[r * QKS + 64 + c4 + 1] = g4.y;
        Qs[r * QKS + 64 + c4 + 2] = g4.z; Qs[r * QKS + 64 + c4 + 3] = g4.w;
    }

    float O[4][4] = {};
    float m[4], l[4];
#pragma unroll
    for (int i = 0; i < 4; i++) { m[i] = -INFINITY; l[i] = 0.0f; }

    for (int jb = 0; jb <= qb; jb++) {
        const int k0 = jb * 64;
        __syncthreads();

        for (int t = tid; t < 64 * 16; t += 256) {
            const int r  = t >> 4;
            const int c4 = (t & 15) << 2;
            const int row = b * L_SEQ + k0 + r;
            const size_t base = (size_t)row * (3 * DMODEL) + h * HDIM + c4;
            float4 k4 = *(const float4*)(g_qkv + base + DMODEL);
            float4 v4 = *(const float4*)(g_qkv + base + 2 * DMODEL);
            float4 g4 = *(const float4*)(kg_in + (size_t)row * DMODEL + h * HDIM + c4);
            Ks[r * QKS + c4 + 0] = k4.x; Ks[r * QKS + c4 + 1] = k4.y;
            Ks[r * QKS + c4 + 2] = k4.z; Ks[r * QKS + c4 + 3] = k4.w;
            Ks[r * QKS + 64 + c4 + 0] = g4.x; Ks[r * QKS + 64 + c4 + 1] = g4.y;
            Ks[r * QKS + 64 + c4 + 2] = g4.z; Ks[r * QKS + 64 + c4 + 3] = g4.w;
            Vs[r * VS + c4 + 0] = v4.x; Vs[r * VS + c4 + 1] = v4.y;
            Vs[r * VS + c4 + 2] = v4.z; Vs[r * VS + c4 + 3] = v4.w;
        }
        __syncthreads();

        float s[4][4] = {};
#pragma unroll 8
        for (int d = 0; d < 128; d++) {
            float a0 = Qs[(ty     ) * QKS + d];
            float a1 = Qs[(ty + 16) * QKS + d];
            float a2 = Qs[(ty + 32) * QKS + d];
            float a3 = Qs[(ty + 48) * QKS + d];
            float b0 = Ks[(tx     ) * QKS + d];
            float b1 = Ks[(tx + 16) * QKS + d];
            float b2 = Ks[(tx + 32) * QKS + d];
            float b3 = Ks[(tx + 48) * QKS + d];
            s[0][0] = fmaf(a0, b0, s[0][0]); s[0][1] = fmaf(a0, b1, s[0][1]);
            s[0][2] = fmaf(a0, b2, s[0][2]); s[0][3] = fmaf(a0, b3, s[0][3]);
            s[1][0] = fmaf(a1, b0, s[1][0]); s[1][1] = fmaf(a1, b1, s[1][1]);
            s[1][2] = fmaf(a1, b2, s[1][2]); s[1][3] = fmaf(a1, b3, s[1][3]);
            s[2][0] = fmaf(a2, b0, s[2][0]); s[2][1] = fmaf(a2, b1, s[2][1]);
            s[2][2] = fmaf(a2, b2, s[2][2]); s[2][3] = fmaf(a2, b3, s[2][3]);
            s[3][0] = fmaf(a3, b0, s[3][0]); s[3][1] = fmaf(a3, b1, s[3][1]);
            s[3][2] = fmaf(a3, b2, s[3][2]); s[3][3] = fmaf(a3, b3, s[3][3]);
        }

        const bool diag = (jb == qb);
#pragma unroll
        for (int i = 0; i < 4; i++)
#pragma unroll
            for (int j = 0; j < 4; j++) {
                float v = s[i][j] * Cmul;
                if (diag && (tx + 16 * j) > (ty + 16 * i)) v = -INFINITY;
                s[i][j] = v;
            }

#pragma unroll
        for (int i = 0; i < 4; i++) {
            float tm = fmaxf(fmaxf(s[i][0], s[i][1]), fmaxf(s[i][2], s[i][3]));
#pragma unroll
            for (int o = 8; o >= 1; o >>= 1)
                tm = fmaxf(tm, __shfl_xor_sync(0xffffffffu, tm, o));
            const float mn = fmaxf(m[i], tm);
            const float alpha = __expf(m[i] - mn);
            m[i] = mn;
            float rs = 0.0f;
#pragma unroll
            for (int j = 0; j < 4; j++) {
                float p = __expf(s[i][j] - mn);
                s[i][j] = p;
                rs += p;
            }
#pragma unroll
            for (int o = 8; o >= 1; o >>= 1)
                rs += __shfl_xor_sync(0xffffffffu, rs, o);
            l[i] = l[i] * alpha + rs;
#pragma unroll
            for (int j = 0; j < 4; j++) O[i][j] *= alpha;
#pragma unroll
            for (int j = 0; j < 4; j++)
                Ps[(ty + 16 * i) * VS + tx + 16 * j] = s[i][j];
        }
        __syncthreads();

#pragma unroll 4
        for (int k = 0; k < 64; k++) {
            float p0 = Ps[(ty     ) * VS + k];
            float p1 = Ps[(ty + 16) * VS + k];
            float p2 = Ps[(ty + 32) * VS + k];
            float p3 = Ps[(ty + 48) * VS + k];
            float v0 = Vs[k * VS + tx     ];
            float v1 = Vs[k * VS + tx + 16];
            float v2 = Vs[k * VS + tx + 32];
            float v3 = Vs[k * VS + tx + 48];
            O[0][0] = fmaf(p0, v0, O[0][0]); O[0][1] = fmaf(p0, v1, O[0][1]);
            O[0][2] = fmaf(p0, v2, O[0][2]); O[0][3] = fmaf(p0, v3, O[0][3]);
            O[1][0] = fmaf(p1, v0, O[1][0]); O[1][1] = fmaf(p1, v1, O[1][1]);
            O[1][2] = fmaf(p1, v2, O[1][2]); O[1][3] = fmaf(p1, v3, O[1][3]);
            O[2][0] = fmaf(p2, v0, O[2][0]); O[2][1] = fmaf(p2, v1, O[2][1]);
            O[2][2] = fmaf(p2, v2, O[2][2]); O[2][3] = fmaf(p2, v3, O[2][3]);
            O[3][0] = fmaf(p3, v0, O[3][0]); O[3][1] = fmaf(p3, v1, O[3][1]);
            O[3][2] = fmaf(p3, v2, O[3][2]); O[3][3] = fmaf(p3, v3, O[3][3]);
        }
    }

    // epilogue: split y into hi/lo bf16
#pragma unroll
    for (int i = 0; i < 4; i++) {
        const float inv = 1.0f / l[i];
        const int row = b * L_SEQ + q0 + ty + 16 * i;
#pragma unroll
        for (int j = 0; j < 4; j++) {
            const size_t idx = (size_t)row * DMODEL + h * HDIM + tx + 16 * j;
            float yv = O[i][j] * inv;
            __nv_bfloat16 hh = __float2bfloat16_rn(yv);
            g_yhi[idx] = hh;
            g_ylo[idx] = __float2bfloat16_rn(yv - __bfloat162float(hh));
        }
    }
}

// ---------------------------------------------------------------------------
extern "C" void kernel_launch(void* const* d_in, const int* in_sizes, int n_in,
                              void* d_out, int out_size)
{
    const float* x     = (const float*)d_in[0];
    const float* q_g   = (const float*)d_in[1];
    const float* k_g   = (const float*)d_in[2];
    const float* W_qkv = (const float*)d_in[3];
    const float* W_out = (const float*)d_in[4];
    float* out = (float*)d_out;

    float* qkv_p;
    __nv_bfloat16 *xhi, *xlo, *yhi, *ylo, *wqh, *wql, *woh, *wol;
    cudaGetSymbolAddress((void**)&qkv_p, g_qkv);
    cudaGetSymbolAddress((void**)&xhi, g_xhi);
    cudaGetSymbolAddress((void**)&xlo, g_xlo);
    cudaGetSymbolAddress((void**)&yhi, g_yhi);
    cudaGetSymbolAddress((void**)&ylo, g_ylo);
    cudaGetSymbolAddress((void**)&wqh, g_wqT_hi);
    cudaGetSymbolAddress((void**)&wql, g_wqT_lo);
    cudaGetSymbolAddress((void**)&woh, g_woT_hi);
    cudaGetSymbolAddress((void**)&wol, g_woT_lo);

    cudaFuncSetAttribute(hmma_gemm_kernel,
                         cudaFuncAttributeMaxDynamicSharedMemorySize, GEMM_SMEM);
    const int attn_smem = (2 * 64 * QKS + 2 * 64 * VS) * (int)sizeof(float);
    cudaFuncSetAttribute(attn_kernel,
                         cudaFuncAttributeMaxDynamicSharedMemorySize, attn_smem);

    // 0) splits / transposes
    {
        int n4 = MROWS * DMODEL / 4;
        cvt_split_kernel<<<(n4 + 255) / 256, 256>>>(x, xhi, xlo, n4);
        dim3 blk(32, 8);
        cvt_transpose_kernel<<<dim3(3 * DMODEL / 32, DMODEL / 32), blk>>>(
            W_qkv, wqh, wql, DMODEL, 3 * DMODEL);
        cvt_transpose_kernel<<<dim3(DMODEL / 32, DMODEL / 32), blk>>>(
            W_out, woh, wol, DMODEL, DMODEL);
    }

    // 1) qkv = x @ W_qkv   (HMMA split-bf16)
    hmma_gemm_kernel<<<dim3(3 * DMODEL / 128, MROWS / 128), 256, GEMM_SMEM>>>(
        MROWS, 3 * DMODEL, DMODEL, xhi, xlo, wqh, wql, qkv_p);

    // 2) attention (fp32 SIMT)
    attn_kernel<<<dim3(L_SEQ / 64, NHEAD, BATCH), 256, attn_smem>>>(q_g, k_g);

    // 3) out = y @ W_out   (HMMA split-bf16)
    hmma_gemm_kernel<<<dim3(DMODEL / 128, MROWS / 128), 256, GEMM_SMEM>>>(
        MROWS, DMODEL, DMODEL, yhi, ylo, woh, wol, out);
}

// round 13
// speedup vs baseline: 5.5817x; 2.3576x over previous
#include <cuda_runtime.h>
#include <cuda_bf16.h>
#include <stdint.h>
#include <math.h>

#define L_SEQ  2048
#define BATCH  2
#define DMODEL 1024
#define NHEAD  16
#define HDIM   64

#define MROWS (BATCH * L_SEQ)         /* 4096 */

// logits = S_raw * 0.125 / ln(2048); base-2 exponent scale:
#define C2SCALE (0.125f / 7.6246189861593985f * 1.4426950408889634f)

// ---------------- scratch (allocation-free rule: __device__ globals) -------
__device__ __nv_bfloat16 g_xhi[MROWS * DMODEL];
__device__ __nv_bfloat16 g_xlo[MROWS * DMODEL];
__device__ __nv_bfloat16 g_yhi[MROWS * DMODEL];
__device__ __nv_bfloat16 g_ylo[MROWS * DMODEL];
__device__ __nv_bfloat16 g_wqT_hi[3 * DMODEL * DMODEL];   // W_qkv^T [3072,1024]
__device__ __nv_bfloat16 g_wqT_lo[3 * DMODEL * DMODEL];
__device__ __nv_bfloat16 g_woT_hi[DMODEL * DMODEL];       // W_out^T [1024,1024]
__device__ __nv_bfloat16 g_woT_lo[DMODEL * DMODEL];
// head-major attention operands: [B,H,L,128] (x|gate along d), V: [B,H,L,64]
__device__ __nv_bfloat16 g_Qhi[BATCH * NHEAD * L_SEQ * 128];
__device__ __nv_bfloat16 g_Qlo[BATCH * NHEAD * L_SEQ * 128];
__device__ __nv_bfloat16 g_Khi[BATCH * NHEAD * L_SEQ * 128];
__device__ __nv_bfloat16 g_Klo[BATCH * NHEAD * L_SEQ * 128];
__device__ __nv_bfloat16 g_Vhi[BATCH * NHEAD * L_SEQ * 64];
__device__ __nv_bfloat16 g_Vlo[BATCH * NHEAD * L_SEQ * 64];

// ---------------- helpers ---------------------------------------------------
__device__ __forceinline__ uint32_t smem_u32(const void* p) {
    uint32_t a;
    asm("{ .reg .u64 t; cvta.to.shared.u64 t, %1; cvt.u32.u64 %0, t; }"
        : "=r"(a) : "l"(p));
    return a;
}
__device__ __forceinline__ void cp16(uint32_t dst, const void* src) {
    asm volatile("cp.async.cg.shared.global [%0], [%1], 16;"
                 :: "r"(dst), "l"(src) : "memory");
}
__device__ __forceinline__ void ldsm_x4(uint32_t* r, uint32_t addr) {
    asm volatile("ldmatrix.sync.aligned.m8n8.x4.shared.b16 {%0,%1,%2,%3}, [%4];"
                 : "=r"(r[0]), "=r"(r[1]), "=r"(r[2]), "=r"(r[3]) : "r"(addr));
}
__device__ __forceinline__ void ldsm_x2(uint32_t* r, uint32_t addr) {
    asm volatile("ldmatrix.sync.aligned.m8n8.x2.shared.b16 {%0,%1}, [%2];"
                 : "=r"(r[0]), "=r"(r[1]) : "r"(addr));
}
__device__ __forceinline__ void ldsm_x2_trans(uint32_t* r, uint32_t addr) {
    asm volatile("ldmatrix.sync.aligned.m8n8.x2.trans.shared.b16 {%0,%1}, [%2];"
                 : "=r"(r[0]), "=r"(r[1]) : "r"(addr));
}
__device__ __forceinline__ void mma_16816(float* d, const uint32_t* a, const uint32_t* b) {
    asm volatile(
        "mma.sync.aligned.m16n8k16.row.col.f32.bf16.bf16.f32 "
        "{%0,%1,%2,%3}, {%4,%5,%6,%7}, {%8,%9}, {%0,%1,%2,%3};"
        : "+f"(d[0]), "+f"(d[1]), "+f"(d[2]), "+f"(d[3])
        : "r"(a[0]), "r"(a[1]), "r"(a[2]), "r"(a[3]), "r"(b[0]), "r"(b[1]));
}
__device__ __forceinline__ uint32_t swz(int r, int cu) {
    return (uint32_t)(r * 128 + ((cu ^ (r & 7)) << 4));
}
// 2^t via FMA-pipe polynomial (t <= 0); MUFU-free.
__device__ __forceinline__ float exp2_poly(float t) {
    t = fmaxf(t, -100.0f);
    int i = __float2int_rn(t);
    float f = t - (float)i;                 // [-0.5, 0.5]
    float p = 1.5403530e-4f;
    p = fmaf(p, f, 1.3333558e-3f);
    p = fmaf(p, f, 9.6181291e-3f);
    p = fmaf(p, f, 5.5504109e-2f);
    p = fmaf(p, f, 2.4022651e-1f);
    p = fmaf(p, f, 6.9314718e-1f);
    p = fmaf(p, f, 1.0f);
    return p * __int_as_float((i + 127) << 23);
}
__device__ __forceinline__ float ex2_mufu(float x) {
    float r;
    asm("ex2.approx.f32 %0, %1;" : "=f"(r) : "f"(x));
    return r;
}
// pack 2 floats -> bf16x2 (p0 low) + residual pair
__device__ __forceinline__ void pack_pair(float p0, float p1, uint32_t& hi, uint32_t& lo) {
    asm("cvt.rn.satfinite.bf16x2.f32 %0, %1, %2;" : "=r"(hi) : "f"(p1), "f"(p0));
    __nv_bfloat162 h2 = *(__nv_bfloat162*)&hi;
    float r0 = p0 - __bfloat162float(h2.x);
    float r1 = p1 - __bfloat162float(h2.y);
    asm("cvt.rn.satfinite.bf16x2.f32 %0, %1, %2;" : "=r"(lo) : "f"(r1), "f"(r0));
}
__device__ __forceinline__ void split_store(__nv_bfloat16* hi, __nv_bfloat16* lo,
                                            float v0, float v1) {
    __nv_bfloat162 h2, l2;
    h2.x = __float2bfloat16_rn(v0); h2.y = __float2bfloat16_rn(v1);
    l2.x = __float2bfloat16_rn(v0 - __bfloat162float(h2.x));
    l2.y = __float2bfloat16_rn(v1 - __bfloat162float(h2.y));
    *(__nv_bfloat162*)hi = h2;
    *(__nv_bfloat162*)lo = l2;
}

// ---------------------------------------------------------------------------
// conversion passes
// ---------------------------------------------------------------------------
__global__ void cvt_split_kernel(const float* __restrict__ in,
                                 __nv_bfloat16* __restrict__ hi,
                                 __nv_bfloat16* __restrict__ lo, int n4)
{
    int i = blockIdx.x * blockDim.x + threadIdx.x;
    if (i >= n4) return;
    float4 v = ((const float4*)in)[i];
    split_store(hi + 4 * (size_t)i, lo + 4 * (size_t)i, v.x, v.y);
    split_store(hi + 4 * (size_t)i + 2, lo + 4 * (size_t)i + 2, v.z, v.w);
}

__global__ void cvt_transpose_kernel(const float* __restrict__ W,
                                     __nv_bfloat16* __restrict__ Thi,
                                     __nv_bfloat16* __restrict__ Tlo,
                                     int K, int N)
{
    __shared__ float t[32][33];
    const int n0 = blockIdx.x * 32, k0 = blockIdx.y * 32;
    const int tx = threadIdx.x, ty = threadIdx.y;
#pragma unroll
    for (int j = 0; j < 32; j += 8)
        t[ty + j][tx] = W[(size_t)(k0 + ty + j) * N + n0 + tx];
    __syncthreads();
#pragma unroll
    for (int j = 0; j < 32; j += 8) {
        float v = t[tx][ty + j];
        size_t o = (size_t)(n0 + ty + j) * K + k0 + tx;
        __nv_bfloat16 hv = __float2bfloat16_rn(v);
        Thi[o] = hv;
        Tlo[o] = __float2bfloat16_rn(v - __bfloat162float(hv));
    }
}

// q_g / k_g -> gate halves (d 64..127) of Q/K arrays; q_g scaled by C2SCALE
__global__ void gqk_split_kernel(const float* __restrict__ qg,
                                 const float* __restrict__ kg)
{
    const int row = blockIdx.x;              // b*L + l
    const int t = threadIdx.x;               // 256
    const int h = t >> 4, grp = t & 15;
    const int b = row >> 11, l = row & 2047;
    const size_t so = (size_t)row * DMODEL + h * HDIM + grp * 4;
    float4 q4 = *(const float4*)(qg + so);
    float4 k4 = *(const float4*)(kg + so);
    const size_t base = ((size_t)(b * NHEAD + h) * L_SEQ + l) * 128 + 64 + grp * 4;
    split_store(g_Qhi + base,     g_Qlo + base,     q4.x * C2SCALE, q4.y * C2SCALE);
    split_store(g_Qhi + base + 2, g_Qlo + base + 2, q4.z * C2SCALE, q4.w * C2SCALE);
    split_store(g_Khi + base,     g_Klo + base,     k4.x, k4.y);
    split_store(g_Khi + base + 2, g_Klo + base + 2, k4.z, k4.w);
}

// qkv GEMM epilogue target: route (row, col) -> split Q/K/V arrays
__device__ __forceinline__ void store_qkv_pair(int row, int col, float v0, float v1) {
    const int b = row >> 11, l = row & 2047;
    const int p = col >> 10, c = col & 1023;
    const int h = c >> 6, d = c & 63;
    const size_t base = (size_t)(b * NHEAD + h) * L_SEQ + l;
    if (p == 0) {
        split_store(g_Qhi + base * 128 + d, g_Qlo + base * 128 + d,
                    v0 * C2SCALE, v1 * C2SCALE);
    } else if (p == 1) {
        split_store(g_Khi + base * 128 + d, g_Klo + base * 128 + d, v0, v1);
    } else {
        split_store(g_Vhi + base * 64 + d, g_Vlo + base * 64 + d, v0, v1);
    }
}

// ---------------------------------------------------------------------------
// HMMA split-bf16 GEMM (R9-validated). MODE 0: write fp32 C. MODE 1: qkv split.
// ---------------------------------------------------------------------------
#define GSTAGE   65536
#define GEMM_SMEM (2 * GSTAGE)

template<int MODE>
__global__ __launch_bounds__(256, 1) void hmma_gemm_kernel(
    int M, int N, int K,
    const __nv_bfloat16* __restrict__ Ahi, const __nv_bfloat16* __restrict__ Alo,
    const __nv_bfloat16* __restrict__ Bhi, const __nv_bfloat16* __restrict__ Blo,
    float* __restrict__ C)
{
    extern __shared__ char smem[];
    const uint32_t sbase = smem_u32(smem);
    const int tid = threadIdx.x;
    const int wid = tid >> 5;
    const int lane = tid & 31;
    const int m0 = blockIdx.y * 128;
    const int n0 = blockIdx.x * 128;
    const int wm = wid & 1;
    const int wn = wid >> 1;

    const __nv_bfloat16* srcs[4] = {
        Ahi + (size_t)m0 * K, Alo + (size_t)m0 * K,
        Bhi + (size_t)n0 * K, Blo + (size_t)n0 * K };

    float acc[4][4][4] = {};
    const int nch = K >> 6;

    auto stage = [&](int c) {
        const int k0 = c << 6;
        const uint32_t sb = sbase + (uint32_t)(c & 1) * GSTAGE;
#pragma unroll
        for (int t = 0; t < 4; t++) {
            const __nv_bfloat16* src = srcs[t] + k0;
#pragma unroll
            for (int i = 0; i < 4; i++) {
                int u = tid + i * 256;
                int r = u >> 3, cu = u & 7;
                cp16(sb + t * 16384 + swz(r, cu), src + (size_t)r * K + cu * 8);
            }
        }
    };

    stage(0);
    asm volatile("cp.async.commit_group;" ::: "memory");

    for (int c = 0; c < nch; c++) {
        if (c + 1 < nch) {
            stage(c + 1);
            asm volatile("cp.async.commit_group;" ::: "memory");
            asm volatile("cp.async.wait_group 1;" ::: "memory");
        } else {
            asm volatile("cp.async.wait_group 0;" ::: "memory");
        }
        __syncthreads();

        const uint32_t sb = sbase + (uint32_t)(c & 1) * GSTAGE;
        const int am = wm * 64, bn = wn * 32;
#pragma unroll
        for (int ks = 0; ks < 4; ks++) {
            uint32_t aH[4][4], aL[4][4], bH[4][2], bL[4][2];
            const int acu = ks * 2 + (lane >> 4);
            const int arow = lane & 15;
#pragma unroll
            for (int mi = 0; mi < 4; mi++) {
                int r = am + mi * 16 + arow;
                uint32_t ad = sb + swz(r, acu);
                ldsm_x4(aH[mi], ad);
                ldsm_x4(aL[mi], ad + 16384);
            }
            const int bcu = ks * 2 + ((lane >> 3) & 1);
            const int brow = lane & 7;
#pragma unroll
            for (int ni = 0; ni < 4; ni++) {
                int r = bn + ni * 8 + brow;
                uint32_t bd = sb + 32768 + swz(r, bcu);
                ldsm_x2(bH[ni], bd);
                ldsm_x2(bL[ni], bd + 16384);
            }
#pragma unroll
            for (int mi = 0; mi < 4; mi++)
#pragma unroll
                for (int ni = 0; ni < 4; ni++) {
                    mma_16816(acc[mi][ni], aH[mi], bH[ni]);
                    mma_16816(acc[mi][ni], aH[mi], bL[ni]);
                    mma_16816(acc[mi][ni], aL[mi], bH[ni]);
                }
        }
        __syncthreads();
    }

#pragma unroll
    for (int mi = 0; mi < 4; mi++) {
        const int row = m0 + wm * 64 + mi * 16 + (lane >> 2);
#pragma unroll
        for (int ni = 0; ni < 4; ni++) {
            const int col = n0 + wn * 32 + ni * 8 + (lane & 3) * 2;
            if (MODE == 0) {
                *(float2*)(C + (size_t)row * N + col) =
                    make_float2(acc[mi][ni][0], acc[mi][ni][1]);
                *(float2*)(C + (size_t)(row + 8) * N + col) =
                    make_float2(acc[mi][ni][2], acc[mi][ni][3]);
            } else {
                store_qkv_pair(row,     col, acc[mi][ni][0], acc[mi][ni][1]);
                store_qkv_pair(row + 8, col, acc[mi][ni][2], acc[mi][ni][3]);
            }
        }
    }
}

// ---------------------------------------------------------------------------
// HMMA flash-attention. CTA = (qb, h, b); 128 q rows, key tiles of 128.
// 8 warps x 16 q rows. 3-term split-bf16 for S and PV. Base-2 online softmax.
// smem: Q(hi/lo, 2 halves) 64KB | K same 64KB | V double-buffered 2x32KB.
// ---------------------------------------------------------------------------
#define AQH 0
#define AQL 32768
#define AKH 65536
#define AKL 98304
#define AVB 131072
#define AT_SMEM (AVB + 2 * 32768)    /* 196608 */

__global__ __launch_bounds__(256, 1) void attn_hmma_kernel()
{
    extern __shared__ char smem[];
    const uint32_t sb = smem_u32(smem);
    const int tid = threadIdx.x;
    const int warp = tid >> 5, lane = tid & 31;
    const int qb = (int)gridDim.x - 1 - (int)blockIdx.x;   // big blocks first
    const int h = blockIdx.y, b = blockIdx.z;
    const int q0 = qb * 128;
    const size_t hb = (size_t)(b * NHEAD + h) * L_SEQ;

    auto load_kv = [&](int t) {
        const int k0 = t * 128;
#pragma unroll
        for (int i = 0; i < 8; i++) {
            int u = tid + i * 256;
            int r = u >> 4, cu = u & 15;
            uint32_t d = (uint32_t)((cu >> 3) * 16384) + swz(r, cu & 7);
            size_t off = (hb + k0 + r) * 128 + cu * 8;
            cp16(sb + AKH + d, g_Khi + off);
            cp16(sb + AKL + d, g_Klo + off);
        }
        const uint32_t vb = sb + AVB + (uint32_t)(t & 1) * 32768;
#pragma unroll
        for (int i = 0; i < 4; i++) {
            int u = tid + i * 256;
            int r = u >> 3, cu = u & 7;
            size_t off = (hb + k0 + r) * 64 + cu * 8;
            cp16(vb + swz(r, cu), g_Vhi + off);
            cp16(vb + 16384 + swz(r, cu), g_Vlo + off);
        }
    };

    // load Q + first K/V
#pragma unroll
    for (int i = 0; i < 8; i++) {
        int u = tid + i * 256;
        int r = u >> 4, cu = u & 15;
        uint32_t d = (uint32_t)((cu >> 3) * 16384) + swz(r, cu & 7);
        size_t off = (hb + q0 + r) * 128 + cu * 8;
        cp16(sb + AQH + d, g_Qhi + off);
        cp16(sb + AQL + d, g_Qlo + off);
    }
    load_kv(0);
    asm volatile("cp.async.commit_group;" ::: "memory");

    float m0 = -1e30f, m1 = -1e30f, l0 = 0.f, l1 = 0.f;
    float O[8][4] = {};

    for (int jt = 0; jt <= qb; jt++) {
        asm volatile("cp.async.wait_group 0;" ::: "memory");
        __syncthreads();

        // ---- S = (Q|Qg) . (K|Kg)^T, 3-term split ----
        float s[16][4] = {};
#pragma unroll
        for (int ks = 0; ks < 8; ks++) {
            const uint32_t halfo = (uint32_t)((ks >> 2) * 16384);
            const int ks4 = ks & 3;
            uint32_t aH[4], aL[4];
            {
                int r = warp * 16 + (lane & 15);
                int acu = ks4 * 2 + (lane >> 4);
                ldsm_x4(aH, sb + AQH + halfo + swz(r, acu));
                ldsm_x4(aL, sb + AQL + halfo + swz(r, acu));
            }
            const int brow = lane & 7;
            const int bcu = ks4 * 2 + ((lane >> 3) & 1);
#pragma unroll
            for (int ni = 0; ni < 16; ni++) {
                uint32_t bH[2], bL[2];
                uint32_t ka = sb + AKH + halfo + swz(ni * 8 + brow, bcu);
                ldsm_x2(bH, ka);
                ldsm_x2(bL, ka + (AKL - AKH));
                mma_16816(s[ni], aH, bH);
                mma_16816(s[ni], aH, bL);
                mma_16816(s[ni], aL, bH);
            }
        }
        __syncthreads();                 // all warps done reading K
        if (jt < qb) {
            load_kv(jt + 1);
            asm volatile("cp.async.commit_group;" ::: "memory");
        }

        // ---- causal mask (diagonal tile only) ----
        if (jt == qb) {
            const int r0 = warp * 16 + (lane >> 2);
#pragma unroll
            for (int ni = 0; ni < 16; ni++) {
                const int c0 = ni * 8 + (lane & 3) * 2;
                if (c0     > r0)     s[ni][0] = -1e30f;
                if (c0 + 1 > r0)     s[ni][1] = -1e30f;
                if (c0     > r0 + 8) s[ni][2] = -1e30f;
                if (c0 + 1 > r0 + 8) s[ni][3] = -1e30f;
            }
        }

        // ---- online softmax (base 2; scale folded into Q) ----
        float tm0 = -1e30f, tm1 = -1e30f;
#pragma unroll
        for (int ni = 0; ni < 16; ni++) {
            tm0 = fmaxf(tm0, fmaxf(s[ni][0], s[ni][1]));
            tm1 = fmaxf(tm1, fmaxf(s[ni][2], s[ni][3]));
        }
        tm0 = fmaxf(tm0, __shfl_xor_sync(0xffffffffu, tm0, 1));
        tm0 = fmaxf(tm0, __shfl_xor_sync(0xffffffffu, tm0, 2));
        tm1 = fmaxf(tm1, __shfl_xor_sync(0xffffffffu, tm1, 1));
        tm1 = fmaxf(tm1, __shfl_xor_sync(0xffffffffu, tm1, 2));
        const float mn0 = fmaxf(m0, tm0), mn1 = fmaxf(m1, tm1);
        const float al0 = ex2_mufu(m0 - mn0), al1 = ex2_mufu(m1 - mn1);
        m0 = mn0; m1 = mn1;
        float rs0 = 0.f, rs1 = 0.f;
#pragma unroll
        for (int ni = 0; ni < 16; ni++) {
            s[ni][0] = exp2_poly(s[ni][0] - mn0); rs0 += s[ni][0];
            s[ni][1] = exp2_poly(s[ni][1] - mn0); rs0 += s[ni][1];
            s[ni][2] = exp2_poly(s[ni][2] - mn1); rs1 += s[ni][2];
            s[ni][3] = exp2_poly(s[ni][3] - mn1); rs1 += s[ni][3];
        }
        l0 = l0 * al0 + rs0;
        l1 = l1 * al1 + rs1;
#pragma unroll
        for (int ni = 0; ni < 8; ni++) {
            O[ni][0] *= al0; O[ni][1] *= al0;
            O[ni][2] *= al1; O[ni][3] *= al1;
        }

        // ---- O += P . V (3-term split) ----
        const uint32_t vb = sb + AVB + (uint32_t)(jt & 1) * 32768;
#pragma unroll
        for (int kk = 0; kk < 8; kk++) {
            uint32_t aPh[4], aPl[4];
            pack_pair(s[2 * kk][0],     s[2 * kk][1],     aPh[0], aPl[0]);
            pack_pair(s[2 * kk][2],     s[2 * kk][3],     aPh[1], aPl[1]);
            pack_pair(s[2 * kk + 1][0], s[2 * kk + 1][1], aPh[2], aPl[2]);
            pack_pair(s[2 * kk + 1][2], s[2 * kk + 1][3], aPh[3], aPl[3]);
            const int vrow = kk * 16 + (lane & 15);
#pragma unroll
            for (int ni = 0; ni < 8; ni++) {
                uint32_t bVh[2], bVl[2];
                uint32_t va = vb + swz(vrow, ni);
                ldsm_x2_trans(bVh, va);
                ldsm_x2_trans(bVl, va + 16384);
                mma_16816(O[ni], aPh, bVh);
                mma_16816(O[ni], aPh, bVl);
                mma_16816(O[ni], aPl, bVh);
            }
        }
    }

    // ---- epilogue: y = O / l, split to bf16 hi/lo ----
    l0 += __shfl_xor_sync(0xffffffffu, l0, 1);
    l0 += __shfl_xor_sync(0xffffffffu, l0, 2);
    l1 += __shfl_xor_sync(0xffffffffu, l1, 1);
    l1 += __shfl_xor_sync(0xffffffffu, l1, 2);
    const float inv0 = 1.0f / l0, inv1 = 1.0f / l1;
    const int row0 = b * L_SEQ + q0 + warp * 16 + (lane >> 2);
#pragma unroll
    for (int ni = 0; ni < 8; ni++) {
        const int d = h * HDIM + ni * 8 + (lane & 3) * 2;
        size_t o0 = (size_t)row0 * DMODEL + d;
        size_t o1 = (size_t)(row0 + 8) * DMODEL + d;
        split_store(g_yhi + o0, g_ylo + o0, O[ni][0] * inv0, O[ni][1] * inv0);
        split_store(g_yhi + o1, g_ylo + o1, O[ni][2] * inv1, O[ni][3] * inv1);
    }
}

// ---------------------------------------------------------------------------
extern "C" void kernel_launch(void* const* d_in, const int* in_sizes, int n_in,
                              void* d_out, int out_size)
{
    const float* x     = (const float*)d_in[0];
    const float* q_g   = (const float*)d_in[1];
    const float* k_g   = (const float*)d_in[2];
    const float* W_qkv = (const float*)d_in[3];
    const float* W_out = (const float*)d_in[4];
    float* out = (float*)d_out;

    __nv_bfloat16 *xhi, *xlo, *yhi, *ylo, *wqh, *wql, *woh, *wol;
    cudaGetSymbolAddress((void**)&xhi, g_xhi);
    cudaGetSymbolAddress((void**)&xlo, g_xlo);
    cudaGetSymbolAddress((void**)&yhi, g_yhi);
    cudaGetSymbolAddress((void**)&ylo, g_ylo);
    cudaGetSymbolAddress((void**)&wqh, g_wqT_hi);
    cudaGetSymbolAddress((void**)&wql, g_wqT_lo);
    cudaGetSymbolAddress((void**)&woh, g_woT_hi);
    cudaGetSymbolAddress((void**)&wol, g_woT_lo);

    cudaFuncSetAttribute(hmma_gemm_kernel<0>,
                         cudaFuncAttributeMaxDynamicSharedMemorySize, GEMM_SMEM);
    cudaFuncSetAttribute(hmma_gemm_kernel<1>,
                         cudaFuncAttributeMaxDynamicSharedMemorySize, GEMM_SMEM);
    cudaFuncSetAttribute(attn_hmma_kernel,
                         cudaFuncAttributeMaxDynamicSharedMemorySize, AT_SMEM);

    // 0) splits / transposes
    {
        int n4 = MROWS * DMODEL / 4;
        cvt_split_kernel<<<(n4 + 255) / 256, 256>>>(x, xhi, xlo, n4);
        dim3 blk(32, 8);
        cvt_transpose_kernel<<<dim3(3 * DMODEL / 32, DMODEL / 32), blk>>>(
            W_qkv, wqh, wql, DMODEL, 3 * DMODEL);
        cvt_transpose_kernel<<<dim3(DMODEL / 32, DMODEL / 32), blk>>>(
            W_out, woh, wol, DMODEL, DMODEL);
        gqk_split_kernel<<<MROWS, 256>>>(q_g, k_g);
    }

    // 1) qkv projection -> split head-major Q/K/V (epilogue fused)
    hmma_gemm_kernel<1><<<dim3(3 * DMODEL / 128, MROWS / 128), 256, GEMM_SMEM>>>(
        MROWS, 3 * DMODEL, DMODEL, xhi, xlo, wqh, wql, nullptr);

    // 2) attention (HMMA flash, dual scores)
    attn_hmma_kernel<<<dim3(L_SEQ / 128, NHEAD, BATCH), 256, AT_SMEM>>>();

    // 3) out = y @ W_out
    hmma_gemm_kernel<0><<<dim3(DMODEL / 128, MROWS / 128), 256, GEMM_SMEM>>>(
        MROWS, DMODEL, DMODEL, yhi, ylo, woh, wol, out);
}